// round 1
// baseline (speedup 1.0000x reference)
#include <cuda_runtime.h>
#include <math.h>

#define HID   32
#define BATCH 2
#define NMAX  55296
#define EMAX  221184
#define COLT  256

// ---- scratch (device globals: allocation-free rule) ----
__device__ float g_t[EMAX * HID];                      //  28 MB
__device__ float g_We[(size_t)EMAX * HID * HID];       // 906 MB, layout [e][o*32+h]
__device__ float g_state[BATCH * NMAX * HID];          //  14 MB
__device__ float g_agg[BATCH * NMAX * HID];            //  14 MB

// ---------------- h0 = ReLU(x@pw1+pb1)@pw2+pb2 ----------------
__global__ void node_mlp_kernel(const float* __restrict__ x,
                                const float* __restrict__ pw1, const float* __restrict__ pb1,
                                const float* __restrict__ pw2, const float* __restrict__ pb2,
                                int rows) {
    __shared__ float w1[HID * HID], w2[HID * HID], b1[HID], b2[HID];
    int tid = threadIdx.x;
    for (int i = tid; i < HID * HID; i += blockDim.x) { w1[i] = pw1[i]; w2[i] = pw2[i]; }
    if (tid < HID) { b1[tid] = pb1[tid]; b2[tid] = pb2[tid]; }
    __syncthreads();
    int warp = tid >> 5, lane = tid & 31;
    int row = blockIdx.x * (blockDim.x >> 5) + warp;
    if (row >= rows) return;
    float xv = x[row * HID + lane];
    float h1 = b1[lane];
#pragma unroll
    for (int k = 0; k < HID; k++)
        h1 = fmaf(__shfl_sync(0xffffffffu, xv, k), w1[k * HID + lane], h1);
    h1 = fmaxf(h1, 0.f);
    float h2 = b2[lane];
#pragma unroll
    for (int k = 0; k < HID; k++)
        h2 = fmaf(__shfl_sync(0xffffffffu, h1, k), w2[k * HID + lane], h2);
    g_state[row * HID + lane] = h2;
}

// ---------------- t = ReLU(er@ew1+eb1)  [E,32] ----------------
__global__ void edge_t_kernel(const float* __restrict__ er,
                              const float* __restrict__ ew1,
                              const float* __restrict__ eb1, int E) {
    int idx = blockIdx.x * blockDim.x + threadIdx.x;
    if (idx >= E * HID) return;
    int e = idx >> 5, l = idx & 31;
    float acc = eb1[l];
#pragma unroll
    for (int m = 0; m < 4; m++)
        acc = fmaf(er[e * 4 + m], ew1[m * HID + l], acc);
    g_t[idx] = fmaxf(acc, 0.f);
}

// ---------------- We = t @ ew2 + eb2, stored transposed [e][o*32+h] ----------------
// grid: (x = edge-group stride, y = 4 column tiles of 256)
// warp handles 4 edges; per k: 4 shfl + 8 LDS + 32 FFMA (register-blocked)
__global__ void we_gemm_kernel(const float* __restrict__ ew2,
                               const float* __restrict__ eb2, int E) {
    __shared__ float ws[HID][COLT];   // 32 KB
    __shared__ float bs[COLT];
    int col0 = blockIdx.y * COLT;
    int tid = threadIdx.x;
    for (int i = tid; i < HID * COLT; i += blockDim.x) {
        int k = i / COLT, c = i % COLT;
        ws[k][c] = ew2[k * (HID * HID) + col0 + c];
    }
    for (int i = tid; i < COLT; i += blockDim.x) bs[i] = eb2[col0 + i];
    __syncthreads();

    int warp = tid >> 5, lane = tid & 31;
    int nwarps = blockDim.x >> 5;
    int groups = (E + 3) >> 2;
    for (int g = blockIdx.x * nwarps + warp; g < groups; g += gridDim.x * nwarps) {
        int e0 = g * 4;
        float t0 = (e0 + 0 < E) ? g_t[(e0 + 0) * HID + lane] : 0.f;
        float t1 = (e0 + 1 < E) ? g_t[(e0 + 1) * HID + lane] : 0.f;
        float t2 = (e0 + 2 < E) ? g_t[(e0 + 2) * HID + lane] : 0.f;
        float t3 = (e0 + 3 < E) ? g_t[(e0 + 3) * HID + lane] : 0.f;
        float acc0[8], acc1[8], acc2[8], acc3[8];
#pragma unroll
        for (int m = 0; m < 8; m++) { acc0[m] = 0.f; acc1[m] = 0.f; acc2[m] = 0.f; acc3[m] = 0.f; }
#pragma unroll
        for (int k = 0; k < HID; k++) {
            float u0 = __shfl_sync(0xffffffffu, t0, k);
            float u1 = __shfl_sync(0xffffffffu, t1, k);
            float u2 = __shfl_sync(0xffffffffu, t2, k);
            float u3 = __shfl_sync(0xffffffffu, t3, k);
#pragma unroll
            for (int m = 0; m < 8; m++) {
                float w = ws[k][m * 32 + lane];
                acc0[m] = fmaf(u0, w, acc0[m]);
                acc1[m] = fmaf(u1, w, acc1[m]);
                acc2[m] = fmaf(u2, w, acc2[m]);
                acc3[m] = fmaf(u3, w, acc3[m]);
            }
        }
        // column j = col0 + m*32 + lane maps to (h = j/32 = blockIdx.y*8+m, o = lane).
        // transposed store addr = e*1024 + o*32 + h  -> 8 contiguous floats per lane.
        float bias[8];
#pragma unroll
        for (int m = 0; m < 8; m++) bias[m] = bs[m * 32 + lane];
#pragma unroll
        for (int i2 = 0; i2 < 4; i2++) {
            int e = e0 + i2;
            if (e >= E) break;
            const float* acc = (i2 == 0) ? acc0 : (i2 == 1) ? acc1 : (i2 == 2) ? acc2 : acc3;
            float4 v0 = make_float4(acc[0] + bias[0], acc[1] + bias[1], acc[2] + bias[2], acc[3] + bias[3]);
            float4 v1 = make_float4(acc[4] + bias[4], acc[5] + bias[5], acc[6] + bias[6], acc[7] + bias[7]);
            float4* dst = (float4*)(g_We + (size_t)e * (HID * HID) + lane * HID + blockIdx.y * 8);
            dst[0] = v0;
            dst[1] = v1;
        }
    }
}

// ---------------- agg init: agg[b,n,l] = conv_b[l] ----------------
__global__ void init_agg_kernel(const float* __restrict__ conv_b, int total) {
    int i = blockIdx.x * blockDim.x + threadIdx.x;
    if (i < total) g_agg[i] = conv_b[i & (HID - 1)];
}

// ---------------- msg + scatter: warp per edge, both batches ----------------
__global__ void msg_kernel(const int* __restrict__ src, const int* __restrict__ dst,
                           int E, int N) {
    int e = (blockIdx.x * blockDim.x + threadIdx.x) >> 5;
    int lane = threadIdx.x & 31;
    if (e >= E) return;
    int s = src[e], d = dst[e];
    float s0 = g_state[s * HID + lane];
    float s1 = g_state[N * HID + s * HID + lane];
    const float4* Wp = (const float4*)(g_We + (size_t)e * (HID * HID) + lane * HID);
    float m0 = 0.f, m1 = 0.f;
#pragma unroll
    for (int q = 0; q < 8; q++) {
        float4 w = Wp[q];
        int h = q * 4;
        float a, b;
        a = __shfl_sync(0xffffffffu, s0, h + 0); b = __shfl_sync(0xffffffffu, s1, h + 0);
        m0 = fmaf(a, w.x, m0); m1 = fmaf(b, w.x, m1);
        a = __shfl_sync(0xffffffffu, s0, h + 1); b = __shfl_sync(0xffffffffu, s1, h + 1);
        m0 = fmaf(a, w.y, m0); m1 = fmaf(b, w.y, m1);
        a = __shfl_sync(0xffffffffu, s0, h + 2); b = __shfl_sync(0xffffffffu, s1, h + 2);
        m0 = fmaf(a, w.z, m0); m1 = fmaf(b, w.z, m1);
        a = __shfl_sync(0xffffffffu, s0, h + 3); b = __shfl_sync(0xffffffffu, s1, h + 3);
        m0 = fmaf(a, w.w, m0); m1 = fmaf(b, w.w, m1);
    }
    atomicAdd(&g_agg[d * HID + lane], m0);
    atomicAdd(&g_agg[N * HID + d * HID + lane], m1);
}

// ---------------- GRU step (x = ReLU(agg), h = state) -> hout ----------------
__global__ void gru_kernel(const float* __restrict__ wih, const float* __restrict__ whh,
                           const float* __restrict__ bih, const float* __restrict__ bhh,
                           float* __restrict__ hout, int rows) {
    __shared__ float WihT[HID][3 * HID];   // [k][j]
    __shared__ float WhhT[HID][3 * HID];
    __shared__ float bi[3 * HID], bh[3 * HID];
    int tid = threadIdx.x;
    for (int i = tid; i < 3 * HID * HID; i += blockDim.x) {
        int j = i / HID, k = i % HID;
        WihT[k][j] = wih[i];
        WhhT[k][j] = whh[i];
    }
    for (int i = tid; i < 3 * HID; i += blockDim.x) { bi[i] = bih[i]; bh[i] = bhh[i]; }
    __syncthreads();
    int warp = tid >> 5, lane = tid & 31;
    int row = blockIdx.x * (blockDim.x >> 5) + warp;
    if (row >= rows) return;
    float a = fmaxf(g_agg[row * HID + lane], 0.f);
    float h = g_state[row * HID + lane];
    float xr = bi[lane], xz = bi[32 + lane], xn = bi[64 + lane];
    float hr = bh[lane], hz = bh[32 + lane], hn = bh[64 + lane];
#pragma unroll
    for (int k = 0; k < HID; k++) {
        float ak = __shfl_sync(0xffffffffu, a, k);
        float hk = __shfl_sync(0xffffffffu, h, k);
        xr = fmaf(ak, WihT[k][lane], xr);
        xz = fmaf(ak, WihT[k][32 + lane], xz);
        xn = fmaf(ak, WihT[k][64 + lane], xn);
        hr = fmaf(hk, WhhT[k][lane], hr);
        hz = fmaf(hk, WhhT[k][32 + lane], hz);
        hn = fmaf(hk, WhhT[k][64 + lane], hn);
    }
    float r = 1.f / (1.f + expf(-(xr + hr)));
    float z = 1.f / (1.f + expf(-(xz + hz)));
    float n = tanhf(xn + r * hn);
    float out = (1.f - z) * n + z * h;
    hout[row * HID + lane] = out;
    g_state[row * HID + lane] = out;   // next step reads state (node == hidden)
}

extern "C" void kernel_launch(void* const* d_in, const int* in_sizes, int n_in,
                              void* d_out, int out_size) {
    const float* x      = (const float*)d_in[0];
    const float* er     = (const float*)d_in[1];
    const float* pw1    = (const float*)d_in[2];
    const float* pb1    = (const float*)d_in[3];
    const float* pw2    = (const float*)d_in[4];
    const float* pb2    = (const float*)d_in[5];
    const float* ew1    = (const float*)d_in[6];
    const float* eb1    = (const float*)d_in[7];
    const float* ew2    = (const float*)d_in[8];
    const float* eb2    = (const float*)d_in[9];
    const float* conv_b = (const float*)d_in[10];
    const float* wih    = (const float*)d_in[11];
    const float* whh    = (const float*)d_in[12];
    const float* bih    = (const float*)d_in[13];
    const float* bhh    = (const float*)d_in[14];
    const int*   esrc   = (const int*)d_in[15];
    const int*   edst   = (const int*)d_in[16];

    int E = in_sizes[15];
    int N = in_sizes[0] / (BATCH * HID);
    int rows = BATCH * N;

    float* state_ptr = nullptr;
    cudaGetSymbolAddress((void**)&state_ptr, g_state);

    // prolog: h0 + t + We (step-invariant)
    node_mlp_kernel<<<(rows + 7) / 8, 256>>>(x, pw1, pb1, pw2, pb2, rows);
    edge_t_kernel<<<(E * HID + 255) / 256, 256>>>(er, ew1, eb1, E);
    {
        dim3 grid(888, 4);
        we_gemm_kernel<<<grid, 256>>>(ew2, eb2, E);
    }

    int aggTotal = rows * HID;
    for (int step = 0; step < 3; step++) {
        init_agg_kernel<<<(aggTotal + 255) / 256, 256>>>(conv_b, aggTotal);
        msg_kernel<<<(E + 7) / 8, 256>>>(esrc, edst, E, N);
        float* hout = (step == 2) ? (float*)d_out : state_ptr;
        gru_kernel<<<(rows + 7) / 8, 256>>>(wih, whh, bih, bhh, hout, rows);
    }
}

// round 2
// speedup vs baseline: 1.2750x; 1.2750x over previous
#include <cuda_runtime.h>
#include <cuda_fp16.h>
#include <math.h>

#define HID   32
#define BATCH 2
#define NMAX  55296
#define EMAX  221184
#define COLT  256

// ---- scratch (device globals: allocation-free rule) ----
__device__ float  g_t[EMAX * HID];                         //  28 MB
__device__ __half g_We[(size_t)EMAX * HID * HID];          // 453 MB, layout [e][o*32+h], fp16
__device__ float  g_state[BATCH * NMAX * HID];             //  14 MB
__device__ float  g_agg[BATCH * NMAX * HID];               //  14 MB

// ---------------- h0 = ReLU(x@pw1+pb1)@pw2+pb2 ----------------
__global__ void node_mlp_kernel(const float* __restrict__ x,
                                const float* __restrict__ pw1, const float* __restrict__ pb1,
                                const float* __restrict__ pw2, const float* __restrict__ pb2,
                                int rows) {
    __shared__ float w1[HID * HID], w2[HID * HID], b1[HID], b2[HID];
    int tid = threadIdx.x;
    for (int i = tid; i < HID * HID; i += blockDim.x) { w1[i] = pw1[i]; w2[i] = pw2[i]; }
    if (tid < HID) { b1[tid] = pb1[tid]; b2[tid] = pb2[tid]; }
    __syncthreads();
    int warp = tid >> 5, lane = tid & 31;
    int row = blockIdx.x * (blockDim.x >> 5) + warp;
    if (row >= rows) return;
    float xv = x[row * HID + lane];
    float h1 = b1[lane];
#pragma unroll
    for (int k = 0; k < HID; k++)
        h1 = fmaf(__shfl_sync(0xffffffffu, xv, k), w1[k * HID + lane], h1);
    h1 = fmaxf(h1, 0.f);
    float h2 = b2[lane];
#pragma unroll
    for (int k = 0; k < HID; k++)
        h2 = fmaf(__shfl_sync(0xffffffffu, h1, k), w2[k * HID + lane], h2);
    g_state[row * HID + lane] = h2;
}

// ---------------- t = ReLU(er@ew1+eb1)  [E,32] ----------------
__global__ void edge_t_kernel(const float* __restrict__ er,
                              const float* __restrict__ ew1,
                              const float* __restrict__ eb1, int E) {
    int idx = blockIdx.x * blockDim.x + threadIdx.x;
    if (idx >= E * HID) return;
    int e = idx >> 5, l = idx & 31;
    float acc = eb1[l];
#pragma unroll
    for (int m = 0; m < 4; m++)
        acc = fmaf(er[e * 4 + m], ew1[m * HID + l], acc);
    g_t[idx] = fmaxf(acc, 0.f);
}

// ---------------- We = t @ ew2 + eb2, fp16, stored transposed [e][o*32+h] ----------------
// grid: (x = edge-group stride, y = 4 column tiles of 256)
// warp handles 4 edges; ReLU zero-skip: each u is warp-uniform -> uniform branch
__global__ void we_gemm_kernel(const float* __restrict__ ew2,
                               const float* __restrict__ eb2, int E) {
    __shared__ float ws[HID][COLT];   // 32 KB
    __shared__ float bs[COLT];
    int col0 = blockIdx.y * COLT;
    int tid = threadIdx.x;
    for (int i = tid; i < HID * COLT; i += blockDim.x) {
        int k = i / COLT, c = i % COLT;
        ws[k][c] = ew2[k * (HID * HID) + col0 + c];
    }
    for (int i = tid; i < COLT; i += blockDim.x) bs[i] = eb2[col0 + i];
    __syncthreads();

    int warp = tid >> 5, lane = tid & 31;
    int nwarps = blockDim.x >> 5;
    int groups = (E + 3) >> 2;
    for (int g = blockIdx.x * nwarps + warp; g < groups; g += gridDim.x * nwarps) {
        int e0 = g * 4;
        float t0 = (e0 + 0 < E) ? g_t[(e0 + 0) * HID + lane] : 0.f;
        float t1 = (e0 + 1 < E) ? g_t[(e0 + 1) * HID + lane] : 0.f;
        float t2 = (e0 + 2 < E) ? g_t[(e0 + 2) * HID + lane] : 0.f;
        float t3 = (e0 + 3 < E) ? g_t[(e0 + 3) * HID + lane] : 0.f;
        float acc0[8], acc1[8], acc2[8], acc3[8];
#pragma unroll
        for (int m = 0; m < 8; m++) { acc0[m] = 0.f; acc1[m] = 0.f; acc2[m] = 0.f; acc3[m] = 0.f; }
#pragma unroll
        for (int k = 0; k < HID; k++) {
            float u0 = __shfl_sync(0xffffffffu, t0, k);
            float u1 = __shfl_sync(0xffffffffu, t1, k);
            float u2 = __shfl_sync(0xffffffffu, t2, k);
            float u3 = __shfl_sync(0xffffffffu, t3, k);
            float w[8];
#pragma unroll
            for (int m = 0; m < 8; m++) w[m] = ws[k][m * 32 + lane];
            // uniform branches (u* identical across warp): skip ReLU zeros (~50% each)
            if (u0 != 0.f) {
#pragma unroll
                for (int m = 0; m < 8; m++) acc0[m] = fmaf(u0, w[m], acc0[m]);
            }
            if (u1 != 0.f) {
#pragma unroll
                for (int m = 0; m < 8; m++) acc1[m] = fmaf(u1, w[m], acc1[m]);
            }
            if (u2 != 0.f) {
#pragma unroll
                for (int m = 0; m < 8; m++) acc2[m] = fmaf(u2, w[m], acc2[m]);
            }
            if (u3 != 0.f) {
#pragma unroll
                for (int m = 0; m < 8; m++) acc3[m] = fmaf(u3, w[m], acc3[m]);
            }
        }
        // column j = col0 + m*32 + lane -> (h = blockIdx.y*8+m, o = lane)
        // transposed fp16 store: g_We[e*1024 + o*32 + h], 8 contiguous halfs = 16B per lane
        float bias[8];
#pragma unroll
        for (int m = 0; m < 8; m++) bias[m] = bs[m * 32 + lane];
#pragma unroll
        for (int i2 = 0; i2 < 4; i2++) {
            int e = e0 + i2;
            if (e >= E) break;
            const float* acc = (i2 == 0) ? acc0 : (i2 == 1) ? acc1 : (i2 == 2) ? acc2 : acc3;
            __half2 p[4];
#pragma unroll
            for (int q = 0; q < 4; q++)
                p[q] = __floats2half2_rn(acc[2 * q] + bias[2 * q], acc[2 * q + 1] + bias[2 * q + 1]);
            uint4* dst = (uint4*)(g_We + (size_t)e * (HID * HID) + lane * HID + blockIdx.y * 8);
            *dst = *(uint4*)p;
        }
    }
}

// ---------------- agg init: agg[b,n,l] = conv_b[l] ----------------
__global__ void init_agg_kernel(const float* __restrict__ conv_b, int total) {
    int i = blockIdx.x * blockDim.x + threadIdx.x;
    if (i < total) g_agg[i] = conv_b[i & (HID - 1)];
}

// ---------------- msg + scatter: warp per edge, both batches, fp16 We ----------------
__global__ void msg_kernel(const int* __restrict__ src, const int* __restrict__ dst,
                           int E, int N) {
    int e = (blockIdx.x * blockDim.x + threadIdx.x) >> 5;
    int lane = threadIdx.x & 31;
    if (e >= E) return;
    int s = src[e], d = dst[e];
    float s0 = g_state[s * HID + lane];
    float s1 = g_state[N * HID + s * HID + lane];
    // lane = o; reads 32 halfs contiguous = 64B = 4x LDG.128
    const uint4* Wp = (const uint4*)(g_We + (size_t)e * (HID * HID) + lane * HID);
    uint4 wv[4];
#pragma unroll
    for (int q = 0; q < 4; q++) wv[q] = Wp[q];
    float m0 = 0.f, m1 = 0.f;
#pragma unroll
    for (int q = 0; q < 4; q++) {
        const __half2* hp = (const __half2*)&wv[q];
#pragma unroll
        for (int j = 0; j < 4; j++) {
            float2 wf = __half22float2(hp[j]);
            int h = q * 8 + j * 2;
            float a0 = __shfl_sync(0xffffffffu, s0, h);
            float b0 = __shfl_sync(0xffffffffu, s1, h);
            float a1 = __shfl_sync(0xffffffffu, s0, h + 1);
            float b1 = __shfl_sync(0xffffffffu, s1, h + 1);
            m0 = fmaf(a0, wf.x, m0); m1 = fmaf(b0, wf.x, m1);
            m0 = fmaf(a1, wf.y, m0); m1 = fmaf(b1, wf.y, m1);
        }
    }
    atomicAdd(&g_agg[d * HID + lane], m0);
    atomicAdd(&g_agg[N * HID + d * HID + lane], m1);
}

// ---------------- GRU step (x = ReLU(agg), h = state) -> hout ----------------
__global__ void gru_kernel(const float* __restrict__ wih, const float* __restrict__ whh,
                           const float* __restrict__ bih, const float* __restrict__ bhh,
                           float* __restrict__ hout, int rows) {
    __shared__ float WihT[HID][3 * HID];   // [k][j]
    __shared__ float WhhT[HID][3 * HID];
    __shared__ float bi[3 * HID], bh[3 * HID];
    int tid = threadIdx.x;
    for (int i = tid; i < 3 * HID * HID; i += blockDim.x) {
        int j = i / HID, k = i % HID;
        WihT[k][j] = wih[i];
        WhhT[k][j] = whh[i];
    }
    for (int i = tid; i < 3 * HID; i += blockDim.x) { bi[i] = bih[i]; bh[i] = bhh[i]; }
    __syncthreads();
    int warp = tid >> 5, lane = tid & 31;
    int row = blockIdx.x * (blockDim.x >> 5) + warp;
    if (row >= rows) return;
    float a = fmaxf(g_agg[row * HID + lane], 0.f);
    float h = g_state[row * HID + lane];
    float xr = bi[lane], xz = bi[32 + lane], xn = bi[64 + lane];
    float hr = bh[lane], hz = bh[32 + lane], hn = bh[64 + lane];
#pragma unroll
    for (int k = 0; k < HID; k++) {
        float ak = __shfl_sync(0xffffffffu, a, k);
        float hk = __shfl_sync(0xffffffffu, h, k);
        xr = fmaf(ak, WihT[k][lane], xr);
        xz = fmaf(ak, WihT[k][32 + lane], xz);
        xn = fmaf(ak, WihT[k][64 + lane], xn);
        hr = fmaf(hk, WhhT[k][lane], hr);
        hz = fmaf(hk, WhhT[k][32 + lane], hz);
        hn = fmaf(hk, WhhT[k][64 + lane], hn);
    }
    float r = 1.f / (1.f + expf(-(xr + hr)));
    float z = 1.f / (1.f + expf(-(xz + hz)));
    float n = tanhf(xn + r * hn);
    float out = (1.f - z) * n + z * h;
    hout[row * HID + lane] = out;
    g_state[row * HID + lane] = out;   // next step reads state (node == hidden)
}

extern "C" void kernel_launch(void* const* d_in, const int* in_sizes, int n_in,
                              void* d_out, int out_size) {
    const float* x      = (const float*)d_in[0];
    const float* er     = (const float*)d_in[1];
    const float* pw1    = (const float*)d_in[2];
    const float* pb1    = (const float*)d_in[3];
    const float* pw2    = (const float*)d_in[4];
    const float* pb2    = (const float*)d_in[5];
    const float* ew1    = (const float*)d_in[6];
    const float* eb1    = (const float*)d_in[7];
    const float* ew2    = (const float*)d_in[8];
    const float* eb2    = (const float*)d_in[9];
    const float* conv_b = (const float*)d_in[10];
    const float* wih    = (const float*)d_in[11];
    const float* whh    = (const float*)d_in[12];
    const float* bih    = (const float*)d_in[13];
    const float* bhh    = (const float*)d_in[14];
    const int*   esrc   = (const int*)d_in[15];
    const int*   edst   = (const int*)d_in[16];

    int E = in_sizes[15];
    int N = in_sizes[0] / (BATCH * HID);
    int rows = BATCH * N;

    float* state_ptr = nullptr;
    cudaGetSymbolAddress((void**)&state_ptr, g_state);

    // prolog: h0 + t + We (step-invariant)
    node_mlp_kernel<<<(rows + 7) / 8, 256>>>(x, pw1, pb1, pw2, pb2, rows);
    edge_t_kernel<<<(E * HID + 255) / 256, 256>>>(er, ew1, eb1, E);
    {
        dim3 grid(888, 4);
        we_gemm_kernel<<<grid, 256>>>(ew2, eb2, E);
    }

    int aggTotal = rows * HID;
    for (int step = 0; step < 3; step++) {
        init_agg_kernel<<<(aggTotal + 255) / 256, 256>>>(conv_b, aggTotal);
        msg_kernel<<<(E + 7) / 8, 256>>>(esrc, edst, E, N);
        float* hout = (step == 2) ? (float*)d_out : state_ptr;
        gru_kernel<<<(rows + 7) / 8, 256>>>(wih, whh, bih, bhh, hout, rows);
    }
}

// round 3
// speedup vs baseline: 1.7653x; 1.3845x over previous
#include <cuda_runtime.h>
#include <cuda_fp16.h>
#include <math.h>

#define HID   32
#define BATCH 2
#define NMAX  55296
#define EMAX  221184
#define COLT  256

typedef unsigned long long ull;

__device__ __forceinline__ void fma2(ull& acc, ull a, ull b) {
    asm("fma.rn.f32x2 %0, %1, %2, %0;" : "+l"(acc) : "l"(a), "l"(b));
}
__device__ __forceinline__ ull pack2(float lo, float hi) {
    ull r; asm("mov.b64 %0, {%1, %2};" : "=l"(r) : "f"(lo), "f"(hi)); return r;
}
__device__ __forceinline__ float2 unpack2(ull v) {
    float2 r; asm("mov.b64 {%0, %1}, %2;" : "=f"(r.x), "=f"(r.y) : "l"(v)); return r;
}

// ---- scratch (device globals: allocation-free rule) ----
__device__ float  g_t[EMAX * HID];                         //  28 MB
__device__ __half g_We[(size_t)EMAX * HID * HID];          // 453 MB, layout [e][o*32+h], fp16
__device__ float  g_state[BATCH * NMAX * HID];             //  14 MB
__device__ float  g_agg[BATCH * NMAX * HID];               //  14 MB

// ---------------- h0 = ReLU(x@pw1+pb1)@pw2+pb2 ----------------
__global__ void node_mlp_kernel(const float* __restrict__ x,
                                const float* __restrict__ pw1, const float* __restrict__ pb1,
                                const float* __restrict__ pw2, const float* __restrict__ pb2,
                                int rows) {
    __shared__ float w1[HID * HID], w2[HID * HID], b1[HID], b2[HID];
    int tid = threadIdx.x;
    for (int i = tid; i < HID * HID; i += blockDim.x) { w1[i] = pw1[i]; w2[i] = pw2[i]; }
    if (tid < HID) { b1[tid] = pb1[tid]; b2[tid] = pb2[tid]; }
    __syncthreads();
    int warp = tid >> 5, lane = tid & 31;
    int row = blockIdx.x * (blockDim.x >> 5) + warp;
    if (row >= rows) return;
    float xv = x[row * HID + lane];
    float h1 = b1[lane];
#pragma unroll
    for (int k = 0; k < HID; k++)
        h1 = fmaf(__shfl_sync(0xffffffffu, xv, k), w1[k * HID + lane], h1);
    h1 = fmaxf(h1, 0.f);
    float h2 = b2[lane];
#pragma unroll
    for (int k = 0; k < HID; k++)
        h2 = fmaf(__shfl_sync(0xffffffffu, h1, k), w2[k * HID + lane], h2);
    g_state[row * HID + lane] = h2;
}

// ---------------- t = ReLU(er@ew1+eb1)  [E,32] ----------------
__global__ void edge_t_kernel(const float* __restrict__ er,
                              const float* __restrict__ ew1,
                              const float* __restrict__ eb1, int E) {
    int idx = blockIdx.x * blockDim.x + threadIdx.x;
    if (idx >= E * HID) return;
    int e = idx >> 5, l = idx & 31;
    float acc = eb1[l];
#pragma unroll
    for (int m = 0; m < 4; m++)
        acc = fmaf(er[e * 4 + m], ew1[m * HID + l], acc);
    g_t[idx] = fmaxf(acc, 0.f);
}

// ---------------- We = t @ ew2 + eb2, fp16, stored transposed [e][o*32+h] ----------------
// f32x2 packed FMA: warp = 4 edges, 256-col tile; per k: 4 shfl + 4 pack + 4 LDS.64 + 16 FMA2
__global__ void we_gemm_kernel(const float* __restrict__ ew2,
                               const float* __restrict__ eb2, int E) {
    // ws2[k][q][lane] = (ew2[k][col0+q*64+lane], ew2[k][col0+q*64+32+lane])  (cols m=2q, m=2q+1)
    __shared__ float2 ws2[HID][4][32];   // 32 KB
    __shared__ float bs[COLT];
    int col0 = blockIdx.y * COLT;
    int tid = threadIdx.x;
    for (int i = tid; i < HID * 128; i += blockDim.x) {
        int k = i >> 7, r = i & 127, q = r >> 5, l = r & 31;
        ws2[k][q][l] = make_float2(ew2[k * (HID * HID) + col0 + q * 64 + l],
                                   ew2[k * (HID * HID) + col0 + q * 64 + 32 + l]);
    }
    for (int i = tid; i < COLT; i += blockDim.x) bs[i] = eb2[col0 + i];
    __syncthreads();

    int warp = tid >> 5, lane = tid & 31;
    int nwarps = blockDim.x >> 5;
    int groups = (E + 3) >> 2;
    for (int g = blockIdx.x * nwarps + warp; g < groups; g += gridDim.x * nwarps) {
        int e0 = g * 4;
        float t0 = (e0 + 0 < E) ? g_t[(e0 + 0) * HID + lane] : 0.f;
        float t1 = (e0 + 1 < E) ? g_t[(e0 + 1) * HID + lane] : 0.f;
        float t2 = (e0 + 2 < E) ? g_t[(e0 + 2) * HID + lane] : 0.f;
        float t3 = (e0 + 3 < E) ? g_t[(e0 + 3) * HID + lane] : 0.f;
        ull acc0[4], acc1[4], acc2[4], acc3[4];
#pragma unroll
        for (int q = 0; q < 4; q++) { acc0[q] = 0ull; acc1[q] = 0ull; acc2[q] = 0ull; acc3[q] = 0ull; }
#pragma unroll
        for (int k = 0; k < HID; k++) {
            float u0 = __shfl_sync(0xffffffffu, t0, k);
            float u1 = __shfl_sync(0xffffffffu, t1, k);
            float u2 = __shfl_sync(0xffffffffu, t2, k);
            float u3 = __shfl_sync(0xffffffffu, t3, k);
            ull p0 = pack2(u0, u0), p1 = pack2(u1, u1), p2 = pack2(u2, u2), p3 = pack2(u3, u3);
#pragma unroll
            for (int q = 0; q < 4; q++) {
                ull w = *(const ull*)&ws2[k][q][lane];
                fma2(acc0[q], p0, w);
                fma2(acc1[q], p1, w);
                fma2(acc2[q], p2, w);
                fma2(acc3[q], p3, w);
            }
        }
        // col m*32+lane -> (h = blockIdx.y*8+m, o = lane); store [e][o*32+h]: 16B/lane contiguous
        float bias[8];
#pragma unroll
        for (int m = 0; m < 8; m++) bias[m] = bs[m * 32 + lane];
#pragma unroll
        for (int i2 = 0; i2 < 4; i2++) {
            int e = e0 + i2;
            if (e >= E) break;
            const ull* accp = (i2 == 0) ? acc0 : (i2 == 1) ? acc1 : (i2 == 2) ? acc2 : acc3;
            float acc[8];
#pragma unroll
            for (int q = 0; q < 4; q++) {
                float2 v = unpack2(accp[q]);
                acc[2 * q] = v.x; acc[2 * q + 1] = v.y;
            }
            __half2 p[4];
#pragma unroll
            for (int q = 0; q < 4; q++)
                p[q] = __floats2half2_rn(acc[2 * q] + bias[2 * q], acc[2 * q + 1] + bias[2 * q + 1]);
            uint4* dst = (uint4*)(g_We + (size_t)e * (HID * HID) + lane * HID + blockIdx.y * 8);
            *dst = *(uint4*)p;
        }
    }
}

// ---------------- agg init (step 0 only): agg[b,n,l] = conv_b[l] ----------------
__global__ void init_agg_kernel(const float* __restrict__ conv_b, int total) {
    int i = blockIdx.x * blockDim.x + threadIdx.x;
    if (i < total) g_agg[i] = conv_b[i & (HID - 1)];
}

// ---------------- msg + scatter: warp per edge, both batches, fp16 We, v4 red ----------------
__global__ void msg_kernel(const int* __restrict__ src, const int* __restrict__ dst,
                           int E, int N) {
    int e = (blockIdx.x * blockDim.x + threadIdx.x) >> 5;
    int lane = threadIdx.x & 31;
    if (e >= E) return;
    int s = src[e], d = dst[e];
    float s0 = g_state[s * HID + lane];
    float s1 = g_state[N * HID + s * HID + lane];
    const uint4* Wp = (const uint4*)(g_We + (size_t)e * (HID * HID) + lane * HID);
    uint4 wv[4];
#pragma unroll
    for (int q = 0; q < 4; q++) wv[q] = Wp[q];
    float m0 = 0.f, m1 = 0.f;
#pragma unroll
    for (int q = 0; q < 4; q++) {
        const __half2* hp = (const __half2*)&wv[q];
#pragma unroll
        for (int j = 0; j < 4; j++) {
            float2 wf = __half22float2(hp[j]);
            int h = q * 8 + j * 2;
            float a0 = __shfl_sync(0xffffffffu, s0, h);
            float b0 = __shfl_sync(0xffffffffu, s1, h);
            float a1 = __shfl_sync(0xffffffffu, s0, h + 1);
            float b1 = __shfl_sync(0xffffffffu, s1, h + 1);
            m0 = fmaf(a0, wf.x, m0); m1 = fmaf(b0, wf.x, m1);
            m0 = fmaf(a1, wf.y, m0); m1 = fmaf(b1, wf.y, m1);
        }
    }
    // transpose: lanes 0-7 -> batch0 quads, lanes 8-15 -> batch1 quads, then red.v4
    int q4 = (lane & 7) * 4;
    float t0 = __shfl_sync(0xffffffffu, m0, q4 + 0);
    float t1 = __shfl_sync(0xffffffffu, m0, q4 + 1);
    float t2 = __shfl_sync(0xffffffffu, m0, q4 + 2);
    float t3 = __shfl_sync(0xffffffffu, m0, q4 + 3);
    float u0 = __shfl_sync(0xffffffffu, m1, q4 + 0);
    float u1 = __shfl_sync(0xffffffffu, m1, q4 + 1);
    float u2 = __shfl_sync(0xffffffffu, m1, q4 + 2);
    float u3 = __shfl_sync(0xffffffffu, m1, q4 + 3);
    if (lane < 16) {
        float v0, v1, v2, v3;
        float* p;
        if (lane < 8) {
            v0 = t0; v1 = t1; v2 = t2; v3 = t3;
            p = &g_agg[d * HID + q4];
        } else {
            v0 = u0; v1 = u1; v2 = u2; v3 = u3;
            p = &g_agg[N * HID + d * HID + q4];
        }
        asm volatile("red.global.add.v4.f32 [%0], {%1, %2, %3, %4};"
                     :: "l"(p), "f"(v0), "f"(v1), "f"(v2), "f"(v3) : "memory");
    }
}

// ---------------- GRU: warp = node, both batches packed in f32x2; reinit agg ----------------
__global__ void gru_kernel(const float* __restrict__ wih, const float* __restrict__ whh,
                           const float* __restrict__ bih, const float* __restrict__ bhh,
                           const float* __restrict__ conv_b,
                           float* __restrict__ dout, int N, int final_step) {
    // W2[g][k][lane] = (wih[(g*32+lane)*32+k], whh[(g*32+lane)*32+k])
    __shared__ float2 W2[3][HID][HID];   // 24 KB
    __shared__ float bi[3 * HID], bh[3 * HID], cb[HID];
    int tid = threadIdx.x;
    for (int i = tid; i < 3 * HID * HID; i += blockDim.x) {
        int g = i >> 10, r = i & 1023, k = r >> 5, l = r & 31;
        int j = g * HID + l;
        W2[g][k][l] = make_float2(wih[j * HID + k], whh[j * HID + k]);
    }
    for (int i = tid; i < 3 * HID; i += blockDim.x) { bi[i] = bih[i]; bh[i] = bhh[i]; }
    if (tid < HID) cb[tid] = conv_b[tid];
    __syncthreads();

    int warp = tid >> 5, lane = tid & 31;
    int n = blockIdx.x * (blockDim.x >> 5) + warp;
    if (n >= N) return;
    int i0 = n * HID + lane;
    int i1 = N * HID + n * HID + lane;
    float a0 = fmaxf(g_agg[i0], 0.f), a1 = fmaxf(g_agg[i1], 0.f);
    float h0 = g_state[i0],          h1 = g_state[i1];

    // packed accumulators (x_acc, h_acc) per gate per batch
    ull r0 = pack2(bi[lane], bh[lane]);
    ull z0 = pack2(bi[32 + lane], bh[32 + lane]);
    ull n0 = pack2(bi[64 + lane], bh[64 + lane]);
    ull r1 = r0, z1 = z0, n1 = n0;
#pragma unroll
    for (int k = 0; k < HID; k++) {
        float ak0 = __shfl_sync(0xffffffffu, a0, k);
        float hk0 = __shfl_sync(0xffffffffu, h0, k);
        float ak1 = __shfl_sync(0xffffffffu, a1, k);
        float hk1 = __shfl_sync(0xffffffffu, h1, k);
        ull xh0 = pack2(ak0, hk0);
        ull xh1 = pack2(ak1, hk1);
        ull wr = *(const ull*)&W2[0][k][lane];
        ull wz = *(const ull*)&W2[1][k][lane];
        ull wn = *(const ull*)&W2[2][k][lane];
        fma2(r0, xh0, wr); fma2(r1, xh1, wr);
        fma2(z0, xh0, wz); fma2(z1, xh1, wz);
        fma2(n0, xh0, wn); fma2(n1, xh1, wn);
    }
    float2 vr0 = unpack2(r0), vz0 = unpack2(z0), vn0 = unpack2(n0);
    float2 vr1 = unpack2(r1), vz1 = unpack2(z1), vn1 = unpack2(n1);

    float rr0 = 1.f / (1.f + expf(-(vr0.x + vr0.y)));
    float zz0 = 1.f / (1.f + expf(-(vz0.x + vz0.y)));
    float nn0 = tanhf(vn0.x + rr0 * vn0.y);
    float out0 = (1.f - zz0) * nn0 + zz0 * h0;

    float rr1 = 1.f / (1.f + expf(-(vr1.x + vr1.y)));
    float zz1 = 1.f / (1.f + expf(-(vz1.x + vz1.y)));
    float nn1 = tanhf(vn1.x + rr1 * vn1.y);
    float out1 = (1.f - zz1) * nn1 + zz1 * h1;

    g_state[i0] = out0;
    g_state[i1] = out1;
    if (final_step) {
        dout[i0] = out0;
        dout[i1] = out1;
    } else {
        // re-init agg for next step's msg scatter
        g_agg[i0] = cb[lane];
        g_agg[i1] = cb[lane];
    }
}

extern "C" void kernel_launch(void* const* d_in, const int* in_sizes, int n_in,
                              void* d_out, int out_size) {
    const float* x      = (const float*)d_in[0];
    const float* er     = (const float*)d_in[1];
    const float* pw1    = (const float*)d_in[2];
    const float* pb1    = (const float*)d_in[3];
    const float* pw2    = (const float*)d_in[4];
    const float* pb2    = (const float*)d_in[5];
    const float* ew1    = (const float*)d_in[6];
    const float* eb1    = (const float*)d_in[7];
    const float* ew2    = (const float*)d_in[8];
    const float* eb2    = (const float*)d_in[9];
    const float* conv_b = (const float*)d_in[10];
    const float* wih    = (const float*)d_in[11];
    const float* whh    = (const float*)d_in[12];
    const float* bih    = (const float*)d_in[13];
    const float* bhh    = (const float*)d_in[14];
    const int*   esrc   = (const int*)d_in[15];
    const int*   edst   = (const int*)d_in[16];

    int E = in_sizes[15];
    int N = in_sizes[0] / (BATCH * HID);
    int rows = BATCH * N;

    // prolog: h0 + t + We (step-invariant)
    node_mlp_kernel<<<(rows + 7) / 8, 256>>>(x, pw1, pb1, pw2, pb2, rows);
    edge_t_kernel<<<(E * HID + 255) / 256, 256>>>(er, ew1, eb1, E);
    {
        dim3 grid(888, 4);
        we_gemm_kernel<<<grid, 256>>>(ew2, eb2, E);
    }

    int aggTotal = rows * HID;
    init_agg_kernel<<<(aggTotal + 255) / 256, 256>>>(conv_b, aggTotal);
    for (int step = 0; step < 3; step++) {
        msg_kernel<<<(E + 7) / 8, 256>>>(esrc, edst, E, N);
        gru_kernel<<<(N + 7) / 8, 256>>>(wih, whh, bih, bhh, conv_b,
                                         (float*)d_out, N, step == 2);
    }
}